// round 16
// baseline (speedup 1.0000x reference)
#include <cuda_runtime.h>
#include <cuda_fp16.h>
#include <cstdint>
#include <cstddef>

// ---------------------------------------------------------------------------
// NonOverlappingConv1d as GEMM, fp16 mma.sync.m16n8k16, fp32 accumulate.
//
//   out[b,o,p] = sum_kidx (W[o][kidx]/sqrt(128)) * x[b, kidx>>1, 2p+(kidx&1)]
//
// R16 change vs R15 (58.1us): warp tile 64x32 -> 64x64. L1 was the binding
// pipe (62.8%); A-fragment LDS (2KB per k16-step per warp) now amortizes over
// 8 n-fragments instead of 4: 192 -> 128 smem-bytes per MMA. 8 warps / 256
// threads (acc = 128 regs), chunks of 32 kidx, smem 96KB.
//
// A (weights): half, fragment-order SMEM (64 KB), staged once, scale folded.
// B (x): LDG float4 -> cvt.rn.f16x2 -> STS.128 into per-c-row half2 layout
//        (1 KB rows, XOR (row&3)<<5); the (2p,2p+1) interleave IS the half2.
//        8 K-chunks of 32 kidx, double-buffered, ldg/compute/sts overlap.
// Fragments: A = LDS.128 conflict-free; B = 2x LDS.32 conflict-free.
// 8 warps = 2(m) x 4(n); warp tile 64 x 64; CTA 128(o) x 256(p); grid 512.
// ---------------------------------------------------------------------------

namespace {
constexpr int kCin = 128, kDin = 8192, kP = 4096, kO = 128, kK = 256;
constexpr int TILE_P = 256;
constexpr int THREADS = 256;
constexpr int NCH = 8;                      // K-chunks of 32 kidx (16 c-rows)
constexpr uint32_t A_BYTES = 65536u;        // 128 x 256 half
constexpr uint32_t B_STAGE = 16384u;        // 16 rows x 1KB (256 half2)
constexpr uint32_t SMEM_BYTES = A_BYTES + 2u * B_STAGE;   // 98304
}  // namespace

__device__ __forceinline__ uint32_t smem_u32(const void* p) {
  uint32_t a;
  asm("{ .reg .u64 t; cvta.to.shared.u64 t, %1; cvt.u32.u64 %0, t; }"
      : "=r"(a) : "l"(p));
  return a;
}
__device__ __forceinline__ uint32_t lds32u(uint32_t a) {
  uint32_t v;
  asm volatile("ld.shared.b32 %0, [%1];" : "=r"(v) : "r"(a));
  return v;
}
__device__ __forceinline__ uint32_t pack_h2(float lo, float hi) {
  uint32_t r;
  asm("cvt.rn.f16x2.f32 %0, %1, %2;" : "=r"(r) : "f"(hi), "f"(lo));
  return r;   // lo -> bits [0:16), hi -> [16:32)
}
__device__ __forceinline__ void sts128(uint32_t a, uint32_t r0, uint32_t r1,
                                       uint32_t r2, uint32_t r3) {
  asm volatile("st.shared.v4.b32 [%0], {%1,%2,%3,%4};"
               :: "r"(a), "r"(r0), "r"(r1), "r"(r2), "r"(r3) : "memory");
}
__device__ __forceinline__ void mma_f16(float d[4], const uint32_t a[4],
                                        const uint32_t b[2]) {
  asm volatile(
      "mma.sync.aligned.m16n8k16.row.col.f32.f16.f16.f32 "
      "{%0,%1,%2,%3}, {%4,%5,%6,%7}, {%8,%9}, {%0,%1,%2,%3};"
      : "+f"(d[0]), "+f"(d[1]), "+f"(d[2]), "+f"(d[3])
      : "r"(a[0]), "r"(a[1]), "r"(a[2]), "r"(a[3]), "r"(b[0]), "r"(b[1]));
}

__global__ __launch_bounds__(THREADS, 1)
void conv1d_fp16_w64x64(const float* __restrict__ x,
                        const float* __restrict__ w,
                        float* __restrict__ out) {
  extern __shared__ char smem[];
  __half* sAh = reinterpret_cast<__half*>(smem);
  const uint32_t sBu = smem_u32(smem) + A_BYTES;

  const int tid = threadIdx.x;
  const int lane = tid & 31;
  const int wid = tid >> 5;
  const int b = blockIdx.y;
  const int p0 = blockIdx.x * TILE_P;

  // ---- B staging: chunk ch = c rows [16ch, 16ch+16). row = tid>>4 (0..15),
  // seg = tid&15. Quarter s: STS.128 at (row*1024 + s*256 + seg*16) ^
  // ((row&3)<<5), sourcing floats [128s+8seg, +8) of the row.
  const int brow = tid >> 4;
  const int bseg = tid & 15;
  float4 stg[8];                       // 32 floats held across compute

  auto ldg_chunk = [&](int ch) {
    const float* xb =
        x + ((size_t)(b * kCin + ch * 16 + brow)) * kDin + 2 * p0 + 8 * bseg;
    #pragma unroll
    for (int s = 0; s < 4; ++s) {
      stg[2 * s]     = *reinterpret_cast<const float4*>(xb + 128 * s);
      stg[2 * s + 1] = *reinterpret_cast<const float4*>(xb + 128 * s + 4);
    }
  };

  auto sts_chunk = [&](int buf) {
    uint32_t base = (sBu + (uint32_t)buf * B_STAGE + (uint32_t)brow * 1024u +
                     (uint32_t)(bseg * 16)) ^ ((uint32_t)(brow & 3) << 5);
    #pragma unroll
    for (int s = 0; s < 4; ++s) {
      sts128(base + (uint32_t)(256 * s),
             pack_h2(stg[2 * s].x, stg[2 * s].y),
             pack_h2(stg[2 * s].z, stg[2 * s].w),
             pack_h2(stg[2 * s + 1].x, stg[2 * s + 1].y),
             pack_h2(stg[2 * s + 1].z, stg[2 * s + 1].w));
    }
  };

  ldg_chunk(0);   // issue early; latency covered by A staging

  // ---- Stage A -> half, fragment order, 1/sqrt(128) folded.
  // Block (mt=o>>4, kt=kidx>>4); r=o&15, c=kidx&15;
  // lane=(r&7)*4+((c&7)>>1); halfpos=4*(c>>3)+2*(r>>3)+(c&1);
  // half index = (mt*16+kt)*256 + lane*8 + halfpos.
  const float scale = 0.08838834764831845f;
  #pragma unroll
  for (int it = 0; it < 32; ++it) {
    int lin = it * THREADS + tid;
    int o = lin >> 6;
    int j = lin & 63;
    float4 w4 = *reinterpret_cast<const float4*>(w + o * kK + 4 * j);
    float v[4] = {w4.x * scale, w4.y * scale, w4.z * scale, w4.w * scale};
    int mt = o >> 4, r = o & 15;
    #pragma unroll
    for (int e = 0; e < 4; ++e) {
      int kidx = 4 * j + e;
      int kt = kidx >> 4, c = kidx & 15;
      int ln = (r & 7) * 4 + ((c & 7) >> 1);
      int hp = 4 * (c >> 3) + 2 * (r >> 3) + (c & 1);
      sAh[(mt * 16 + kt) * 256 + ln * 8 + hp] = __float2half_rn(v[e]);
    }
  }

  sts_chunk(0);
  __syncthreads();
  ldg_chunk(1);

  // ---- Warp tiling: 8 warps = 2(m) x 4(n); warp tile 64(o) x 64(p).
  const int wm = (wid >> 2) * 64;            // 0 or 64
  const int wn = (wid & 3) * 64;             // 0,64,128,192
  const int gid = lane >> 2, tq = lane & 3;
  const __half* sAw = sAh + (wm >> 4) * 16 * 256;

  float acc[4][8][4];
  #pragma unroll
  for (int i = 0; i < 4; ++i)
    #pragma unroll
    for (int j2 = 0; j2 < 8; ++j2)
      #pragma unroll
      for (int r2 = 0; r2 < 4; ++r2) acc[i][j2][r2] = 0.f;

  // B frag (kstep j in chunk, nt): reg0 row 8j+tq, reg1 row 8j+tq+4 (+4096B);
  // loc = (4*(wn + 8nt + gid)) ^ (tq<<5)  [XOR after the nt add].
  const uint32_t brow0 = (uint32_t)tq * 1024u;
  const uint32_t bq0 = (uint32_t)(4 * (wn + gid));
  const uint32_t bxor = (uint32_t)tq << 5;

  auto compute_chunk = [&](int ch, int buf) {
    const uint32_t bb = sBu + (uint32_t)buf * B_STAGE + brow0;
    #pragma unroll
    for (int j = 0; j < 2; ++j) {            // 2 k16-steps per chunk
      const int kt = ch * 2 + j;
      uint32_t afr[4][4];
      #pragma unroll
      for (int mt2 = 0; mt2 < 4; ++mt2) {
        uint4 av = *reinterpret_cast<const uint4*>(
            sAw + (mt2 * 16 + kt) * 256 + lane * 8);
        afr[mt2][0] = av.x; afr[mt2][1] = av.y;
        afr[mt2][2] = av.z; afr[mt2][3] = av.w;
      }
      const uint32_t rb = bb + (uint32_t)(8 * j) * 1024u;
      uint32_t bfr[8][2];
      #pragma unroll
      for (int nt = 0; nt < 8; ++nt) {
        uint32_t loc = (bq0 + (uint32_t)(32 * nt)) ^ bxor;
        bfr[nt][0] = lds32u(rb + loc);
        bfr[nt][1] = lds32u(rb + 4096u + loc);
      }
      #pragma unroll
      for (int mt2 = 0; mt2 < 4; ++mt2)
        #pragma unroll
        for (int nt = 0; nt < 8; ++nt)
          mma_f16(acc[mt2][nt], afr[mt2], bfr[nt]);
    }
  };

  // ---- Mainloop: 8 chunks, double-buffered (stg held across compute).
  #pragma unroll 1
  for (int ch = 0; ch < NCH; ++ch) {
    compute_chunk(ch, ch & 1);
    if (ch + 1 < NCH) {
      sts_chunk((ch + 1) & 1);
      __syncthreads();
      if (ch + 2 < NCH) ldg_chunk(ch + 2);
    }
  }

  // ---- Epilogue (scale folded in A): float2 stores.
  // D frag: c0:(g,2tq) c1:(g,2tq+1) c2:(g+8,2tq) c3:(g+8,2tq+1)
  float* ob = out + (size_t)b * kO * kP;
  #pragma unroll
  for (int mt2 = 0; mt2 < 4; ++mt2) {
    int o0 = wm + mt2 * 16 + gid;
    #pragma unroll
    for (int nt = 0; nt < 8; ++nt) {
      int p = p0 + wn + nt * 8 + 2 * tq;
      *reinterpret_cast<float2*>(ob + (size_t)o0 * kP + p) =
          make_float2(acc[mt2][nt][0], acc[mt2][nt][1]);
      *reinterpret_cast<float2*>(ob + (size_t)(o0 + 8) * kP + p) =
          make_float2(acc[mt2][nt][2], acc[mt2][nt][3]);
    }
  }
}

extern "C" void kernel_launch(void* const* d_in, const int* in_sizes, int n_in,
                              void* d_out, int out_size) {
  const float* x = (const float*)d_in[0];
  const float* w = (const float*)d_in[1];
  if (n_in >= 2 && in_sizes[0] == kO * kK) {   // defensive operand id by size
    const float* t = x; x = w; w = t;
  }
  (void)out_size;

  cudaFuncSetAttribute(conv1d_fp16_w64x64,
                       cudaFuncAttributeMaxDynamicSharedMemorySize, SMEM_BYTES);

  dim3 grid(kP / TILE_P, 32);   // (16, 32) = 512 CTAs
  conv1d_fp16_w64x64<<<grid, THREADS, SMEM_BYTES>>>(x, w, (float*)d_out);
}